// round 13
// baseline (speedup 1.0000x reference)
#include <cuda_runtime.h>
#include <cuda_bf16.h>
#include <cstdint>

#define GRAPHS 4096
#define NPG 18
#define NNODES (GRAPHS * NPG)
#define FIN 1536
#define EPERG 306
#define SLOPE 0.01f
#define BN_EPS 1e-5f

#define NKSTEP (FIN / 16)            // 96 k-steps of 16
#define PIT 68                       // graph_kernel smem pitch (floats): 68%32=4 -> conflict-free

// Scratch
__device__ float g_P1[(size_t)NNODES * 32];
__device__ uint32_t g_fragH[NKSTEP * 256];
__device__ uint32_t g_fragL[NKSTEP * 256];
// W3 fragments: [ks(4)][nt(16)][lane(32)][which(2)] uint32
__device__ uint32_t g_frag3H[4 * 16 * 32 * 2];
__device__ uint32_t g_frag3L[4 * 16 * 32 * 2];

// ---------------------------------------------------------------------------
__device__ __forceinline__ void mma16816(float* c, const uint32_t* a, const uint32_t* b) {
    asm volatile("mma.sync.aligned.m16n8k16.row.col.f32.bf16.bf16.f32 "
        "{%0,%1,%2,%3}, {%4,%5,%6,%7}, {%8,%9}, {%0,%1,%2,%3};"
        : "+f"(c[0]), "+f"(c[1]), "+f"(c[2]), "+f"(c[3])
        : "r"(a[0]), "r"(a[1]), "r"(a[2]), "r"(a[3]), "r"(b[0]), "r"(b[1]));
}
__device__ __forceinline__ uint32_t pack_bf16x2(float lo, float hi) {
    uint32_t r;
    asm("cvt.rn.bf16x2.f32 %0, %1, %2;" : "=r"(r) : "f"(hi), "f"(lo));
    return r;
}
__device__ __forceinline__ void split2(float2 v, uint32_t& hi, uint32_t& lo) {
    hi = pack_bf16x2(v.x, v.y);
    float f0 = __uint_as_float(hi << 16);
    float f1 = __uint_as_float(hi & 0xFFFF0000u);
    lo = pack_bf16x2(v.x - f0, v.y - f1);
}
__device__ __forceinline__ float lrelu(float v) { return v >= 0.f ? v : SLOPE * v; }

// ---- packed f32x2 helpers ----
__device__ __forceinline__ uint64_t bcast2(float a) {
    uint64_t r;
    asm("mov.b64 %0, {%1, %1};" : "=l"(r) : "f"(a));
    return r;
}
__device__ __forceinline__ uint64_t ffma2(uint64_t a, uint64_t b, uint64_t c) {
    uint64_t d;
    asm("fma.rn.f32x2 %0, %1, %2, %3;" : "=l"(d) : "l"(a), "l"(b), "l"(c));
    return d;
}
__device__ __forceinline__ float2 unpack2(uint64_t v) {
    float2 f;
    asm("mov.b64 {%0, %1}, %2;" : "=f"(f.x), "=f"(f.y) : "l"(v));
    return f;
}
__device__ __forceinline__ float4 up4(ulonglong2 v) {
    float2 a = unpack2(v.x), b = unpack2(v.y);
    return make_float4(a.x, a.y, b.x, b.y);
}
__device__ __forceinline__ float4 bn_lrelu4(float4 acc, float4 bb, float4 s, float4 t) {
    float4 o;
    o.x = lrelu(fmaf(acc.x + bb.x, s.x, t.x));
    o.y = lrelu(fmaf(acc.y + bb.y, s.y, t.y));
    o.z = lrelu(fmaf(acc.z + bb.z, s.z, t.z));
    o.w = lrelu(fmaf(acc.w + bb.w, s.w, t.w));
    return o;
}

// ---------------------------------------------------------------------------
// Kernel 0: W1 fragment builder (identical to R8).
// ---------------------------------------------------------------------------
__global__ __launch_bounds__(256) void wconv_kernel(const float* __restrict__ W1) {
    int t = blockIdx.x * 256 + threadIdx.x;
    int s = t >> 6;
    int rem = t & 63;
    int j = rem >> 5, lane = rem & 31;
    uint32_t h[4], l[4];
#pragma unroll
    for (int i = 0; i < 4; i++) {
        int ri = j * 4 + i;
        int nt = ri >> 1, which = ri & 1;
        int n = nt * 8 + (lane >> 2);
        int k = s * 16 + (lane & 3) * 2 + which * 8;
        float x0 = W1[(size_t)k * 32 + n];
        float x1 = W1[(size_t)(k + 1) * 32 + n];
        split2(make_float2(x0, x1), h[i], l[i]);
    }
    int o = s * 256 + j * 128 + lane * 4;
    *(uint4*)(g_fragH + o) = make_uint4(h[0], h[1], h[2], h[3]);
    *(uint4*)(g_fragL + o) = make_uint4(l[0], l[1], l[2], l[3]);
}

// ---------------------------------------------------------------------------
// Kernel 0b: W3 fragment builder. 4096 threads, one frag-reg each.
// frag[ks][nt][lane][which] = bf16x2(W3[k][n], W3[k+1][n]),
//   n = nt*8 + lane>>2, k = ks*16 + (lane&3)*2 + which*8
// ---------------------------------------------------------------------------
__global__ __launch_bounds__(256) void wconv3_kernel(const float* __restrict__ W3) {
    int t = blockIdx.x * 256 + threadIdx.x;        // 0..4095
    int which = t & 1, lane = (t >> 1) & 31, nt = (t >> 6) & 15, ks = t >> 10;
    int n = nt * 8 + (lane >> 2);
    int k = ks * 16 + (lane & 3) * 2 + which * 8;
    float x0 = W3[(size_t)k * 128 + n];
    float x1 = W3[(size_t)(k + 1) * 128 + n];
    uint32_t h, l;
    split2(make_float2(x0, x1), h, l);
    g_frag3H[t] = h;
    g_frag3L[t] = l;
}

// ---------------------------------------------------------------------------
// Kernel 1: P1 = X @ W1 (identical to R8).
// ---------------------------------------------------------------------------
__global__ __launch_bounds__(256) void gemm1_mma_kernel(const float* __restrict__ X)
{
    const int tid = threadIdx.x;
    const int wid = tid >> 5;
    const int lane = tid & 31;
    const int row0 = blockIdx.x * 128;
    const int r = row0 + wid * 16 + (lane >> 2);

    const float* xr0 = X + (size_t)r * FIN + (lane & 3) * 2;
    const float* xr1 = xr0 + (size_t)8 * FIN;
    const uint4* fH = (const uint4*)g_fragH + lane;
    const uint4* fL = (const uint4*)g_fragL + lane;

    float acc[4][4];
#pragma unroll
    for (int nt = 0; nt < 4; nt++)
#pragma unroll
        for (int q = 0; q < 4; q++) acc[nt][q] = 0.f;

#pragma unroll 2
    for (int s = 0; s < NKSTEP; s++) {
        const int k = s * 16;
        float2 a0 = *(const float2*)(xr0 + k);
        float2 a1 = *(const float2*)(xr1 + k);
        float2 a2 = *(const float2*)(xr0 + k + 8);
        float2 a3 = *(const float2*)(xr1 + k + 8);
        uint4 h0 = fH[s * 64];
        uint4 h1 = fH[s * 64 + 32];
        uint4 l0 = fL[s * 64];
        uint4 l1 = fL[s * 64 + 32];

        uint32_t ahi[4], alo[4];
        split2(a0, ahi[0], alo[0]);
        split2(a1, ahi[1], alo[1]);
        split2(a2, ahi[2], alo[2]);
        split2(a3, ahi[3], alo[3]);

        uint32_t bhi[8] = {h0.x, h0.y, h0.z, h0.w, h1.x, h1.y, h1.z, h1.w};
        uint32_t blo[8] = {l0.x, l0.y, l0.z, l0.w, l1.x, l1.y, l1.z, l1.w};

#pragma unroll
        for (int nt = 0; nt < 4; nt++) {
            mma16816(acc[nt], ahi, bhi + nt * 2);
            mma16816(acc[nt], ahi, blo + nt * 2);
            mma16816(acc[nt], alo, bhi + nt * 2);
        }
    }

    {
        int cb = (lane & 3) * 2;
#pragma unroll
        for (int nt = 0; nt < 4; nt++) {
            *(float2*)(g_P1 + (size_t)r * 32 + nt * 8 + cb) =
                make_float2(acc[nt][0], acc[nt][1]);
            *(float2*)(g_P1 + (size_t)(r + 8) * 32 + nt * 8 + cb) =
                make_float2(acc[nt][2], acc[nt][3]);
        }
    }
}

// ---------------------------------------------------------------------------
// Kernel 2: TWO graphs per CTA. Layer-3 GEMM+BN+lrelu+pool via mma.sync
// with fused shfl-reduce epilogue (no part buffer, no pool phase).
// ---------------------------------------------------------------------------
__global__ __launch_bounds__(288, 3) void graph_kernel(
    const float* __restrict__ ew,
    const float* __restrict__ b1, const float* __restrict__ g1,
    const float* __restrict__ be1, const float* __restrict__ rm1, const float* __restrict__ rv1,
    const float* __restrict__ W2, const float* __restrict__ b2, const float* __restrict__ g2,
    const float* __restrict__ be2, const float* __restrict__ rm2, const float* __restrict__ rv2,
    const float* __restrict__ b3, const float* __restrict__ g3,
    const float* __restrict__ be3, const float* __restrict__ rm3, const float* __restrict__ rv3,
    const float* __restrict__ fW1, const float* __restrict__ fb1,
    const float* __restrict__ fW2, const float* __restrict__ fb2,
    const float* __restrict__ fW3, const float* __restrict__ fb3,
    const float* __restrict__ fW4, const float* __restrict__ fb4,
    float* __restrict__ out)
{
    __shared__ __align__(16) float Wm[2][18][20];
    __shared__ __align__(16) float A[2][18][20];
    __shared__ float dinv[2][18];
    __shared__ __align__(16) float bns1[32], bnb1[32];
    __shared__ __align__(16) float bns2[64], bnb2[64];
    __shared__ __align__(16) float bns3[128], bnb3[128];
    __shared__ __align__(16) float bufA[48 * PIT];    // rows 0..35 = g3m, 36..47 zero pad
    __shared__ __align__(16) float bufB[36 * PIT];
    __shared__ __align__(16) float pvec[2][128];
    __shared__ __align__(16) float p2[2][2][64];
    __shared__ float m1[2][64], m2[2][32], m3[2][16];

    const int g0 = blockIdx.x * 2;
    const int tid = threadIdx.x;
    const int wid = tid >> 5;
    const int lane = tid & 31;

    if (tid < 32) {
        float s = g1[tid] * rsqrtf(rv1[tid] + BN_EPS);
        bns1[tid] = s; bnb1[tid] = be1[tid] - rm1[tid] * s;
    } else if (tid < 96) {
        int f = tid - 32;
        float s = g2[f] * rsqrtf(rv2[f] + BN_EPS);
        bns2[f] = s; bnb2[f] = be2[f] - rm2[f] * s;
    } else if (tid < 224) {
        int f = tid - 96;
        float s = g3[f] * rsqrtf(rv3[f] + BN_EPS);
        bns3[f] = s; bnb3[f] = be3[f] - rm3[f] * s;
    }

    for (int t = tid; t < 648; t += 288) {
        int g = t / 324, rem = t - g * 324;
        int s = rem / 18, d = rem - s * 18;
        Wm[g][s][d] = (s == d) ? 1.0f
                    : ew[(size_t)(g0 + g) * EPERG + s * 17 + d - (d > s ? 1 : 0)];
    }
    {
        int g = tid / 144, rem = tid - g * 144;
        int r = rem >> 3, f4 = rem & 7;
        *(float4*)&bufA[(g * 18 + r) * PIT + f4 * 4] =
            *(const float4*)(g_P1 + ((size_t)(g0 + g) * 18 + r) * 32 + f4 * 4);
    }
    __syncthreads();
    if (tid < 36) {
        int g = tid / 18, c = tid - g * 18;
        float sum = 0.f;
#pragma unroll
        for (int s = 0; s < 18; s++) sum += Wm[g][s][c];
        dinv[g][c] = rsqrtf(sum);
    }
    __syncthreads();
    for (int t = tid; t < 648; t += 288) {
        int g = t / 324, rem = t - g * 324;
        int c = rem / 18, r = rem - c * 18;
        A[g][c][r] = dinv[g][r] * dinv[g][c] * Wm[g][r][c];
    }
    __syncthreads();

    // --- layer1: h1 = lrelu(bn1(A @ P1 + b1)) -> bufB (width 32) ---
    {
        int g = tid / 144, rem = tid - g * 144;
        int c = rem >> 3, f4 = rem & 7;
        ulonglong2 acc = make_ulonglong2(0ULL, 0ULL);
#pragma unroll
        for (int r = 0; r < 18; r++) {
            uint64_t av = bcast2(A[g][c][r]);
            ulonglong2 h = *(const ulonglong2*)&bufA[(g * 18 + r) * PIT + f4 * 4];
            acc.x = ffma2(av, h.x, acc.x);
            acc.y = ffma2(av, h.y, acc.y);
        }
        float4 o = bn_lrelu4(up4(acc), __ldg((const float4*)b1 + f4),
                             *(float4*)&bns1[f4 * 4], *(float4*)&bnb1[f4 * 4]);
        *(float4*)&bufB[(g * 18 + c) * PIT + f4 * 4] = o;
    }
    __syncthreads();

    // --- layer2 agg-first: g2m = A @ h1 -> bufA (width 32) ---
    {
        int g = tid / 144, rem = tid - g * 144;
        int c = rem >> 3, f4 = rem & 7;
        ulonglong2 acc = make_ulonglong2(0ULL, 0ULL);
#pragma unroll
        for (int r = 0; r < 18; r++) {
            uint64_t av = bcast2(A[g][c][r]);
            ulonglong2 h = *(const ulonglong2*)&bufB[(g * 18 + r) * PIT + f4 * 4];
            acc.x = ffma2(av, h.x, acc.x);
            acc.y = ffma2(av, h.y, acc.y);
        }
        *(ulonglong2*)&bufA[(g * 18 + c) * PIT + f4 * 4] = acc;
    }
    __syncthreads();

    // --- layer2 GEMM: h2 = lrelu(bn2(g2m @ W2 + b2)) -> bufB (width 64) ---
    {
        int c = tid >> 4, f4 = tid & 15;
        ulonglong2 acc0 = make_ulonglong2(0ULL, 0ULL);
        ulonglong2 acc1 = make_ulonglong2(0ULL, 0ULL);
#pragma unroll 8
        for (int k = 0; k < 32; k++) {
            ulonglong2 w = __ldg((const ulonglong2*)(W2 + (size_t)k * 64) + f4);
            uint64_t a0 = bcast2(bufA[(0 * 18 + c) * PIT + k]);
            uint64_t a1 = bcast2(bufA[(1 * 18 + c) * PIT + k]);
            acc0.x = ffma2(a0, w.x, acc0.x);
            acc0.y = ffma2(a0, w.y, acc0.y);
            acc1.x = ffma2(a1, w.x, acc1.x);
            acc1.y = ffma2(a1, w.y, acc1.y);
        }
        float4 bb = __ldg((const float4*)b2 + f4);
        float4 s = *(float4*)&bns2[f4 * 4];
        float4 t = *(float4*)&bnb2[f4 * 4];
        *(float4*)&bufB[(0 * 18 + c) * PIT + f4 * 4] = bn_lrelu4(up4(acc0), bb, s, t);
        *(float4*)&bufB[(1 * 18 + c) * PIT + f4 * 4] = bn_lrelu4(up4(acc1), bb, s, t);
    }
    __syncthreads();

    // --- layer3 agg-first: g3m = A @ h2 -> bufA rows 0..35; zero pad 36..47 ---
    {
        int c = tid >> 4, f4 = tid & 15;
#pragma unroll
        for (int g = 0; g < 2; g++) {
            ulonglong2 acc = make_ulonglong2(0ULL, 0ULL);
#pragma unroll
            for (int r = 0; r < 18; r++) {
                uint64_t av = bcast2(A[g][c][r]);
                ulonglong2 h = *(const ulonglong2*)&bufB[(g * 18 + r) * PIT + f4 * 4];
                acc.x = ffma2(av, h.x, acc.x);
                acc.y = ffma2(av, h.y, acc.y);
            }
            *(ulonglong2*)&bufA[(g * 18 + c) * PIT + f4 * 4] = acc;
        }
        for (int t = tid; t < 12 * 64; t += 288) {
            int r = 36 + t / 64, k = t - (t / 64) * 64;
            bufA[r * PIT + k] = 0.f;
        }
    }
    __syncthreads();

    // --- layer3 GEMM (mma.sync split-bf16) + BN + lrelu + pool, fused ---
    // warps 0..7: each owns n-tiles nt = 2w, 2w+1. M = 48 rows (3 m-tiles).
    if (wid < 8) {
        float cacc[2][3][4];
#pragma unroll
        for (int n2 = 0; n2 < 2; n2++)
#pragma unroll
            for (int mt = 0; mt < 3; mt++)
#pragma unroll
                for (int q = 0; q < 4; q++) cacc[n2][mt][q] = 0.f;

        const uint2* f3H = (const uint2*)g_frag3H;
        const uint2* f3L = (const uint2*)g_frag3L;
        const int rbase = lane >> 2;
        const int kbase = (lane & 3) * 2;

#pragma unroll
        for (int ks = 0; ks < 4; ks++) {
            uint32_t ahi[3][4], alo[3][4];
#pragma unroll
            for (int mt = 0; mt < 3; mt++) {
                int rlo = mt * 16 + rbase;
                int kk = ks * 16 + kbase;
                float2 p0 = *(const float2*)&bufA[rlo * PIT + kk];
                float2 p1 = *(const float2*)&bufA[(rlo + 8) * PIT + kk];
                float2 p2v = *(const float2*)&bufA[rlo * PIT + kk + 8];
                float2 p3 = *(const float2*)&bufA[(rlo + 8) * PIT + kk + 8];
                split2(p0, ahi[mt][0], alo[mt][0]);
                split2(p1, ahi[mt][1], alo[mt][1]);
                split2(p2v, ahi[mt][2], alo[mt][2]);
                split2(p3, ahi[mt][3], alo[mt][3]);
            }
#pragma unroll
            for (int n2 = 0; n2 < 2; n2++) {
                int nt = wid * 2 + n2;
                uint2 bh = f3H[(ks * 16 + nt) * 32 + lane];
                uint2 bl = f3L[(ks * 16 + nt) * 32 + lane];
                uint32_t bhv[2] = {bh.x, bh.y};
                uint32_t blv[2] = {bl.x, bl.y};
#pragma unroll
                for (int mt = 0; mt < 3; mt++) {
                    mma16816(cacc[n2][mt], ahi[mt], bhv);
                    mma16816(cacc[n2][mt], ahi[mt], blv);
                    mma16816(cacc[n2][mt], alo[mt], bhv);
                }
            }
        }

        // fused epilogue: BN + lrelu + per-graph pool via shfl reduce
#pragma unroll
        for (int n2 = 0; n2 < 2; n2++) {
            int nt = wid * 2 + n2;
            int col0 = nt * 8 + (lane & 3) * 2;
            float2 b3v = __ldg((const float2*)(b3 + col0));
            float2 sv = *(const float2*)&bns3[col0];
            float2 tv = *(const float2*)&bnb3[col0];
            float s00 = 0.f, s01 = 0.f, s10 = 0.f, s11 = 0.f;
#pragma unroll
            for (int mt = 0; mt < 3; mt++) {
                int rlo = mt * 16 + rbase;
                int rhi = rlo + 8;
                float v0 = lrelu(fmaf(cacc[n2][mt][0] + b3v.x, sv.x, tv.x));
                float v1 = lrelu(fmaf(cacc[n2][mt][1] + b3v.y, sv.y, tv.y));
                float v2 = lrelu(fmaf(cacc[n2][mt][2] + b3v.x, sv.x, tv.x));
                float v3 = lrelu(fmaf(cacc[n2][mt][3] + b3v.y, sv.y, tv.y));
                if (rlo < 18)      { s00 += v0; s01 += v1; }
                else if (rlo < 36) { s10 += v0; s11 += v1; }
                if (rhi < 18)      { s00 += v2; s01 += v3; }
                else if (rhi < 36) { s10 += v2; s11 += v3; }
            }
#pragma unroll
            for (int d = 4; d <= 16; d <<= 1) {
                s00 += __shfl_xor_sync(0xFFFFFFFFu, s00, d);
                s01 += __shfl_xor_sync(0xFFFFFFFFu, s01, d);
                s10 += __shfl_xor_sync(0xFFFFFFFFu, s10, d);
                s11 += __shfl_xor_sync(0xFFFFFFFFu, s11, d);
            }
            if (lane < 4) {
                pvec[0][col0]     = s00 * (1.0f / 18.0f);
                pvec[0][col0 + 1] = s01 * (1.0f / 18.0f);
                pvec[1][col0]     = s10 * (1.0f / 18.0f);
                pvec[1][col0 + 1] = s11 * (1.0f / 18.0f);
            }
        }
    }
    __syncthreads();

    // --- MLP head ---
    if (tid < 256) {
        int g = tid >> 7, rem = tid & 127;
        int ks = rem >> 6, f = rem & 63;
        float acc = 0.f;
#pragma unroll
        for (int k = ks * 64; k < ks * 64 + 64; k++)
            acc = fmaf(pvec[g][k], __ldg(fW1 + (size_t)k * 64 + f), acc);
        p2[g][ks][f] = acc;
    }
    __syncthreads();
    if (tid < 128) {
        int g = tid >> 6, f = tid & 63;
        m1[g][f] = lrelu(p2[g][0][f] + p2[g][1][f] + __ldg(fb1 + f));
    }
    __syncthreads();
    if (tid < 64) {
        int g = tid >> 5, f = tid & 31;
        float acc = __ldg(fb2 + f);
#pragma unroll
        for (int k = 0; k < 64; k++)
            acc = fmaf(m1[g][k], __ldg(fW2 + (size_t)k * 32 + f), acc);
        m2[g][f] = lrelu(acc);
    }
    __syncthreads();
    if (tid < 32) {
        int g = tid >> 4, f = tid & 15;
        float acc = __ldg(fb3 + f);
#pragma unroll
        for (int k = 0; k < 32; k++)
            acc = fmaf(m2[g][k], __ldg(fW3 + (size_t)k * 16 + f), acc);
        m3[g][f] = lrelu(acc);
    }
    __syncthreads();
    {
        if (wid < 2) {
            float p = (lane < 16) ? m3[wid][lane] * __ldg(fW4 + lane) : 0.f;
#pragma unroll
            for (int off = 8; off > 0; off >>= 1)
                p += __shfl_down_sync(0xFFFFFFFFu, p, off);
            if (lane == 0) out[g0 + wid] = p + __ldg(fb4);
        }
    }
}

// ---------------------------------------------------------------------------
extern "C" void kernel_launch(void* const* d_in, const int* in_sizes, int n_in,
                              void* d_out, int out_size)
{
    (void)in_sizes; (void)n_in; (void)out_size;
    const float* x   = (const float*)d_in[0];
    const float* ew  = (const float*)d_in[2];
    const float* W1  = (const float*)d_in[4];
    const float* b1  = (const float*)d_in[5];
    const float* g1  = (const float*)d_in[6];
    const float* be1 = (const float*)d_in[7];
    const float* rm1 = (const float*)d_in[8];
    const float* rv1 = (const float*)d_in[9];
    const float* W2  = (const float*)d_in[10];
    const float* b2  = (const float*)d_in[11];
    const float* g2  = (const float*)d_in[12];
    const float* be2 = (const float*)d_in[13];
    const float* rm2 = (const float*)d_in[14];
    const float* rv2 = (const float*)d_in[15];
    const float* W3  = (const float*)d_in[16];
    const float* b3  = (const float*)d_in[17];
    const float* g3  = (const float*)d_in[18];
    const float* be3 = (const float*)d_in[19];
    const float* rm3 = (const float*)d_in[20];
    const float* rv3 = (const float*)d_in[21];
    const float* fW1 = (const float*)d_in[22];
    const float* fb1 = (const float*)d_in[23];
    const float* fW2 = (const float*)d_in[24];
    const float* fb2 = (const float*)d_in[25];
    const float* fW3 = (const float*)d_in[26];
    const float* fb3 = (const float*)d_in[27];
    const float* fW4 = (const float*)d_in[28];
    const float* fb4 = (const float*)d_in[29];

    wconv_kernel<<<24, 256>>>(W1);
    wconv3_kernel<<<16, 256>>>(W3);
    gemm1_mma_kernel<<<NNODES / 128, 256>>>(x);
    graph_kernel<<<GRAPHS / 2, 288>>>(ew,
        b1, g1, be1, rm1, rv1,
        W2, b2, g2, be2, rm2, rv2,
        b3, g3, be3, rm3, rv3,
        fW1, fb1, fW2, fb2, fW3, fb3, fW4, fb4,
        (float*)d_out);
}

// round 14
// speedup vs baseline: 1.3858x; 1.3858x over previous
#include <cuda_runtime.h>
#include <cuda_bf16.h>
#include <cstdint>

#define GRAPHS 4096
#define NPG 18
#define NNODES (GRAPHS * NPG)
#define FIN 1536
#define EPERG 306
#define SLOPE 0.01f
#define BN_EPS 1e-5f

#define NKSTEP (FIN / 16)            // 96 k-steps of 16
#define TP 42                        // transposed-buffer pitch (floats)

// Scratch
__device__ float g_P1[(size_t)NNODES * 32];
__device__ uint32_t g_fragH[NKSTEP * 256];
__device__ uint32_t g_fragL[NKSTEP * 256];

// ---------------------------------------------------------------------------
__device__ __forceinline__ void mma16816(float* c, const uint32_t* a, const uint32_t* b) {
    asm volatile("mma.sync.aligned.m16n8k16.row.col.f32.bf16.bf16.f32 "
        "{%0,%1,%2,%3}, {%4,%5,%6,%7}, {%8,%9}, {%0,%1,%2,%3};"
        : "+f"(c[0]), "+f"(c[1]), "+f"(c[2]), "+f"(c[3])
        : "r"(a[0]), "r"(a[1]), "r"(a[2]), "r"(a[3]), "r"(b[0]), "r"(b[1]));
}
__device__ __forceinline__ uint32_t pack_bf16x2(float lo, float hi) {
    uint32_t r;
    asm("cvt.rn.bf16x2.f32 %0, %1, %2;" : "=r"(r) : "f"(hi), "f"(lo));
    return r;
}
__device__ __forceinline__ void split2(float2 v, uint32_t& hi, uint32_t& lo) {
    hi = pack_bf16x2(v.x, v.y);
    float f0 = __uint_as_float(hi << 16);
    float f1 = __uint_as_float(hi & 0xFFFF0000u);
    lo = pack_bf16x2(v.x - f0, v.y - f1);
}
__device__ __forceinline__ float lrelu(float v) { return v >= 0.f ? v : SLOPE * v; }

// ---- packed f32x2 helpers ----
__device__ __forceinline__ uint64_t bcast2(float a) {
    uint64_t r;
    asm("mov.b64 %0, {%1, %1};" : "=l"(r) : "f"(a));
    return r;
}
__device__ __forceinline__ uint64_t ffma2(uint64_t a, uint64_t b, uint64_t c) {
    uint64_t d;
    asm("fma.rn.f32x2 %0, %1, %2, %3;" : "=l"(d) : "l"(a), "l"(b), "l"(c));
    return d;
}
__device__ __forceinline__ float2 unpack2(uint64_t v) {
    float2 f;
    asm("mov.b64 {%0, %1}, %2;" : "=f"(f.x), "=f"(f.y) : "l"(v));
    return f;
}
__device__ __forceinline__ float4 up4(ulonglong2 v) {
    float2 a = unpack2(v.x), b = unpack2(v.y);
    return make_float4(a.x, a.y, b.x, b.y);
}
__device__ __forceinline__ float4 bn_lrelu4(float4 acc, float4 bb, float4 s, float4 t) {
    float4 o;
    o.x = lrelu(fmaf(acc.x + bb.x, s.x, t.x));
    o.y = lrelu(fmaf(acc.y + bb.y, s.y, t.y));
    o.z = lrelu(fmaf(acc.z + bb.z, s.z, t.z));
    o.w = lrelu(fmaf(acc.w + bb.w, s.w, t.w));
    return o;
}

// ---------------------------------------------------------------------------
// Kernel 0: W1 fragment builder (identical to R8).
// ---------------------------------------------------------------------------
__global__ __launch_bounds__(256) void wconv_kernel(const float* __restrict__ W1) {
    int t = blockIdx.x * 256 + threadIdx.x;
    int s = t >> 6;
    int rem = t & 63;
    int j = rem >> 5, lane = rem & 31;
    uint32_t h[4], l[4];
#pragma unroll
    for (int i = 0; i < 4; i++) {
        int ri = j * 4 + i;
        int nt = ri >> 1, which = ri & 1;
        int n = nt * 8 + (lane >> 2);
        int k = s * 16 + (lane & 3) * 2 + which * 8;
        float x0 = W1[(size_t)k * 32 + n];
        float x1 = W1[(size_t)(k + 1) * 32 + n];
        split2(make_float2(x0, x1), h[i], l[i]);
    }
    int o = s * 256 + j * 128 + lane * 4;
    *(uint4*)(g_fragH + o) = make_uint4(h[0], h[1], h[2], h[3]);
    *(uint4*)(g_fragL + o) = make_uint4(l[0], l[1], l[2], l[3]);
}

// ---------------------------------------------------------------------------
// Kernel 1: P1 = X @ W1 (identical to R8).
// ---------------------------------------------------------------------------
__global__ __launch_bounds__(256) void gemm1_mma_kernel(const float* __restrict__ X)
{
    const int tid = threadIdx.x;
    const int wid = tid >> 5;
    const int lane = tid & 31;
    const int row0 = blockIdx.x * 128;
    const int r = row0 + wid * 16 + (lane >> 2);

    const float* xr0 = X + (size_t)r * FIN + (lane & 3) * 2;
    const float* xr1 = xr0 + (size_t)8 * FIN;
    const uint4* fH = (const uint4*)g_fragH + lane;
    const uint4* fL = (const uint4*)g_fragL + lane;

    float acc[4][4];
#pragma unroll
    for (int nt = 0; nt < 4; nt++)
#pragma unroll
        for (int q = 0; q < 4; q++) acc[nt][q] = 0.f;

#pragma unroll 2
    for (int s = 0; s < NKSTEP; s++) {
        const int k = s * 16;
        float2 a0 = *(const float2*)(xr0 + k);
        float2 a1 = *(const float2*)(xr1 + k);
        float2 a2 = *(const float2*)(xr0 + k + 8);
        float2 a3 = *(const float2*)(xr1 + k + 8);
        uint4 h0 = fH[s * 64];
        uint4 h1 = fH[s * 64 + 32];
        uint4 l0 = fL[s * 64];
        uint4 l1 = fL[s * 64 + 32];

        uint32_t ahi[4], alo[4];
        split2(a0, ahi[0], alo[0]);
        split2(a1, ahi[1], alo[1]);
        split2(a2, ahi[2], alo[2]);
        split2(a3, ahi[3], alo[3]);

        uint32_t bhi[8] = {h0.x, h0.y, h0.z, h0.w, h1.x, h1.y, h1.z, h1.w};
        uint32_t blo[8] = {l0.x, l0.y, l0.z, l0.w, l1.x, l1.y, l1.z, l1.w};

#pragma unroll
        for (int nt = 0; nt < 4; nt++) {
            mma16816(acc[nt], ahi, bhi + nt * 2);
            mma16816(acc[nt], ahi, blo + nt * 2);
            mma16816(acc[nt], alo, bhi + nt * 2);
        }
    }

    {
        int cb = (lane & 3) * 2;
#pragma unroll
        for (int nt = 0; nt < 4; nt++) {
            *(float2*)(g_P1 + (size_t)r * 32 + nt * 8 + cb) =
                make_float2(acc[nt][0], acc[nt][1]);
            *(float2*)(g_P1 + (size_t)(r + 8) * 32 + nt * 8 + cb) =
                make_float2(acc[nt][2], acc[nt][3]);
        }
    }
}

// ---------------------------------------------------------------------------
// Kernel 2: TWO graphs per CTA (R8 body). GEMM row-operands staged TRANSPOSED
// (bufT overlaying the part buffer) so the k-loops read warp-uniform
// LDS broadcasts instead of 2-4 scalar broadcasts per k.
// ---------------------------------------------------------------------------
__global__ __launch_bounds__(288, 4) void graph_kernel(
    const float* __restrict__ ew,
    const float* __restrict__ b1, const float* __restrict__ g1,
    const float* __restrict__ be1, const float* __restrict__ rm1, const float* __restrict__ rv1,
    const float* __restrict__ W2, const float* __restrict__ b2, const float* __restrict__ g2,
    const float* __restrict__ be2, const float* __restrict__ rm2, const float* __restrict__ rv2,
    const float* __restrict__ W3, const float* __restrict__ b3, const float* __restrict__ g3,
    const float* __restrict__ be3, const float* __restrict__ rm3, const float* __restrict__ rv3,
    const float* __restrict__ fW1, const float* __restrict__ fb1,
    const float* __restrict__ fW2, const float* __restrict__ fb2,
    const float* __restrict__ fW3, const float* __restrict__ fb3,
    const float* __restrict__ fW4, const float* __restrict__ fb4,
    float* __restrict__ out)
{
    __shared__ __align__(16) float Wm[2][18][20];
    __shared__ __align__(16) float A[2][18][20];
    __shared__ float dinv[2][18];
    __shared__ __align__(16) float bns1[32], bnb1[32];
    __shared__ __align__(16) float bns2[64], bnb2[64];
    __shared__ __align__(16) float bns3[128], bnb3[128];
    __shared__ __align__(16) float bufA[2 * 18 * 64];
    __shared__ __align__(16) float bufB[2 * 18 * 64];
    __shared__ __align__(16) float scr[64 * TP];   // union: bufT2 / bufT3 / part(2304)
    __shared__ __align__(16) float pvec[2][128];
    __shared__ __align__(16) float p2[2][2][64];
    __shared__ float m1[2][64], m2[2][32], m3[2][16];

    float* part = scr;                 // part[cg][g][f] = scr[cg*256 + g*128 + f]

    const int g0 = blockIdx.x * 2;
    const int tid = threadIdx.x;

    if (tid < 32) {
        float s = g1[tid] * rsqrtf(rv1[tid] + BN_EPS);
        bns1[tid] = s; bnb1[tid] = be1[tid] - rm1[tid] * s;
    } else if (tid < 96) {
        int f = tid - 32;
        float s = g2[f] * rsqrtf(rv2[f] + BN_EPS);
        bns2[f] = s; bnb2[f] = be2[f] - rm2[f] * s;
    } else if (tid < 224) {
        int f = tid - 96;
        float s = g3[f] * rsqrtf(rv3[f] + BN_EPS);
        bns3[f] = s; bnb3[f] = be3[f] - rm3[f] * s;
    }

    for (int t = tid; t < 648; t += 288) {
        int g = t / 324, rem = t - g * 324;
        int s = rem / 18, d = rem - s * 18;
        Wm[g][s][d] = (s == d) ? 1.0f
                    : ew[(size_t)(g0 + g) * EPERG + s * 17 + d - (d > s ? 1 : 0)];
    }
    {
        int g = tid / 144, rem = tid - g * 144;
        int r = rem >> 3, f4 = rem & 7;
        *(float4*)&bufA[(g * 18 + r) * 64 + f4 * 4] =
            *(const float4*)(g_P1 + ((size_t)(g0 + g) * 18 + r) * 32 + f4 * 4);
    }
    __syncthreads();
    if (tid < 36) {
        int g = tid / 18, c = tid - g * 18;
        float sum = 0.f;
#pragma unroll
        for (int s = 0; s < 18; s++) sum += Wm[g][s][c];
        dinv[g][c] = rsqrtf(sum);
    }
    __syncthreads();
    for (int t = tid; t < 648; t += 288) {
        int g = t / 324, rem = t - g * 324;
        int c = rem / 18, r = rem - c * 18;
        A[g][c][r] = dinv[g][r] * dinv[g][c] * Wm[g][r][c];
    }
    __syncthreads();

    // --- layer1: h1 = lrelu(bn1(A @ P1 + b1)) -> bufB (width 32) ---
    {
        int g = tid / 144, rem = tid - g * 144;
        int c = rem >> 3, f4 = rem & 7;
        ulonglong2 acc = make_ulonglong2(0ULL, 0ULL);
#pragma unroll
        for (int r = 0; r < 18; r++) {
            uint64_t av = bcast2(A[g][c][r]);
            ulonglong2 h = *(const ulonglong2*)&bufA[(g * 18 + r) * 64 + f4 * 4];
            acc.x = ffma2(av, h.x, acc.x);
            acc.y = ffma2(av, h.y, acc.y);
        }
        float4 o = bn_lrelu4(up4(acc), __ldg((const float4*)b1 + f4),
                             *(float4*)&bns1[f4 * 4], *(float4*)&bnb1[f4 * 4]);
        *(float4*)&bufB[(g * 18 + c) * 64 + f4 * 4] = o;
    }
    __syncthreads();

    // --- layer2 agg-first: g2m = A @ h1 -> TRANSPOSED scr[k][2c+g] ---
    {
        int g = tid / 144, rem = tid - g * 144;
        int c = rem >> 3, f4 = rem & 7;
        ulonglong2 acc = make_ulonglong2(0ULL, 0ULL);
#pragma unroll
        for (int r = 0; r < 18; r++) {
            uint64_t av = bcast2(A[g][c][r]);
            ulonglong2 h = *(const ulonglong2*)&bufB[(g * 18 + r) * 64 + f4 * 4];
            acc.x = ffma2(av, h.x, acc.x);
            acc.y = ffma2(av, h.y, acc.y);
        }
        float4 v = up4(acc);
        int base = 2 * c + g;
        scr[(f4 * 4 + 0) * TP + base] = v.x;
        scr[(f4 * 4 + 1) * TP + base] = v.y;
        scr[(f4 * 4 + 2) * TP + base] = v.z;
        scr[(f4 * 4 + 3) * TP + base] = v.w;
    }
    __syncthreads();

    // --- layer2 GEMM: h2 = lrelu(bn2(g2m @ W2 + b2)) -> bufB (width 64) ---
    {
        int c = tid >> 4, f4 = tid & 15;
        ulonglong2 acc0 = make_ulonglong2(0ULL, 0ULL);
        ulonglong2 acc1 = make_ulonglong2(0ULL, 0ULL);
#pragma unroll 8
        for (int k = 0; k < 32; k++) {
            ulonglong2 w = __ldg((const ulonglong2*)(W2 + (size_t)k * 64) + f4);
            float2 av = *(const float2*)&scr[k * TP + 2 * c];   // (g0, g1) broadcast
            uint64_t a0 = bcast2(av.x);
            uint64_t a1 = bcast2(av.y);
            acc0.x = ffma2(a0, w.x, acc0.x);
            acc0.y = ffma2(a0, w.y, acc0.y);
            acc1.x = ffma2(a1, w.x, acc1.x);
            acc1.y = ffma2(a1, w.y, acc1.y);
        }
        float4 bb = __ldg((const float4*)b2 + f4);
        float4 s = *(float4*)&bns2[f4 * 4];
        float4 t = *(float4*)&bnb2[f4 * 4];
        *(float4*)&bufB[(0 * 18 + c) * 64 + f4 * 4] = bn_lrelu4(up4(acc0), bb, s, t);
        *(float4*)&bufB[(1 * 18 + c) * 64 + f4 * 4] = bn_lrelu4(up4(acc1), bb, s, t);
    }
    __syncthreads();

    // --- layer3 agg-first: g3m = A @ h2 -> TRANSPOSED scr[k][18g + c] ---
    {
        int c = tid >> 4, f4 = tid & 15;
#pragma unroll
        for (int g = 0; g < 2; g++) {
            ulonglong2 acc = make_ulonglong2(0ULL, 0ULL);
#pragma unroll
            for (int r = 0; r < 18; r++) {
                uint64_t av = bcast2(A[g][c][r]);
                ulonglong2 h = *(const ulonglong2*)&bufB[(g * 18 + r) * 64 + f4 * 4];
                acc.x = ffma2(av, h.x, acc.x);
                acc.y = ffma2(av, h.y, acc.y);
            }
            float4 v = up4(acc);
            int base = 18 * g + c;
            scr[(f4 * 4 + 0) * TP + base] = v.x;
            scr[(f4 * 4 + 1) * TP + base] = v.y;
            scr[(f4 * 4 + 2) * TP + base] = v.z;
            scr[(f4 * 4 + 3) * TP + base] = v.w;
        }
    }
    __syncthreads();

    // --- layer3 GEMM + BN + lrelu + pool partial (warp-uniform row broadcasts) ---
    {
        int cg = tid >> 5, f4 = tid & 31;
        int ra = cg * 2;
        ulonglong2 a00 = make_ulonglong2(0ULL, 0ULL), a01 = a00, a10 = a00, a11 = a00;
#pragma unroll 8
        for (int k = 0; k < 64; k++) {
            ulonglong2 w = __ldg((const ulonglong2*)(W3 + (size_t)k * 128) + f4);
            float2 v0 = *(const float2*)&scr[k * TP + ra];        // g0: rows ra, ra+1
            float2 v1 = *(const float2*)&scr[k * TP + 18 + ra];   // g1
            uint64_t v00 = bcast2(v0.x);
            uint64_t v01 = bcast2(v0.y);
            uint64_t v10 = bcast2(v1.x);
            uint64_t v11 = bcast2(v1.y);
            a00.x = ffma2(v00, w.x, a00.x); a00.y = ffma2(v00, w.y, a00.y);
            a01.x = ffma2(v01, w.x, a01.x); a01.y = ffma2(v01, w.y, a01.y);
            a10.x = ffma2(v10, w.x, a10.x); a10.y = ffma2(v10, w.y, a10.y);
            a11.x = ffma2(v11, w.x, a11.x); a11.y = ffma2(v11, w.y, a11.y);
        }
        float4 bb = __ldg((const float4*)b3 + f4);
        float4 s = *(float4*)&bns3[f4 * 4];
        float4 t = *(float4*)&bnb3[f4 * 4];
        float4 o00 = bn_lrelu4(up4(a00), bb, s, t);
        float4 o01 = bn_lrelu4(up4(a01), bb, s, t);
        float4 o10 = bn_lrelu4(up4(a10), bb, s, t);
        float4 o11 = bn_lrelu4(up4(a11), bb, s, t);
        __syncthreads();   // scr (g3m) reads complete before part overlay
        *(float4*)&part[cg * 256 + 0 * 128 + f4 * 4] =
            make_float4(o00.x + o01.x, o00.y + o01.y, o00.z + o01.z, o00.w + o01.w);
        *(float4*)&part[cg * 256 + 1 * 128 + f4 * 4] =
            make_float4(o10.x + o11.x, o10.y + o11.y, o10.z + o11.z, o10.w + o11.w);
    }
    __syncthreads();

    // --- pool reduce ---
    if (tid < 256) {
        int g = tid >> 7, f = tid & 127;
        float s = 0.f;
#pragma unroll
        for (int cg = 0; cg < 9; cg++) s += part[cg * 256 + g * 128 + f];
        pvec[g][f] = s * (1.0f / 18.0f);
    }
    __syncthreads();

    // --- MLP head ---
    if (tid < 256) {
        int g = tid >> 7, rem = tid & 127;
        int ks = rem >> 6, f = rem & 63;
        float acc = 0.f;
#pragma unroll
        for (int k = ks * 64; k < ks * 64 + 64; k++)
            acc = fmaf(pvec[g][k], __ldg(fW1 + (size_t)k * 64 + f), acc);
        p2[g][ks][f] = acc;
    }
    __syncthreads();
    if (tid < 128) {
        int g = tid >> 6, f = tid & 63;
        m1[g][f] = lrelu(p2[g][0][f] + p2[g][1][f] + __ldg(fb1 + f));
    }
    __syncthreads();
    if (tid < 64) {
        int g = tid >> 5, f = tid & 31;
        float acc = __ldg(fb2 + f);
#pragma unroll
        for (int k = 0; k < 64; k++)
            acc = fmaf(m1[g][k], __ldg(fW2 + (size_t)k * 32 + f), acc);
        m2[g][f] = lrelu(acc);
    }
    __syncthreads();
    if (tid < 32) {
        int g = tid >> 4, f = tid & 15;
        float acc = __ldg(fb3 + f);
#pragma unroll
        for (int k = 0; k < 32; k++)
            acc = fmaf(m2[g][k], __ldg(fW3 + (size_t)k * 16 + f), acc);
        m3[g][f] = lrelu(acc);
    }
    __syncthreads();
    {
        int wid = tid >> 5, lane = tid & 31;
        if (wid < 2) {
            float p = (lane < 16) ? m3[wid][lane] * __ldg(fW4 + lane) : 0.f;
#pragma unroll
            for (int off = 8; off > 0; off >>= 1)
                p += __shfl_down_sync(0xFFFFFFFFu, p, off);
            if (lane == 0) out[g0 + wid] = p + __ldg(fb4);
        }
    }
}

// ---------------------------------------------------------------------------
extern "C" void kernel_launch(void* const* d_in, const int* in_sizes, int n_in,
                              void* d_out, int out_size)
{
    (void)in_sizes; (void)n_in; (void)out_size;
    const float* x   = (const float*)d_in[0];
    const float* ew  = (const float*)d_in[2];
    const float* W1  = (const float*)d_in[4];
    const float* b1  = (const float*)d_in[5];
    const float* g1  = (const float*)d_in[6];
    const float* be1 = (const float*)d_in[7];
    const float* rm1 = (const float*)d_in[8];
    const float* rv1 = (const float*)d_in[9];
    const float* W2  = (const float*)d_in[10];
    const float* b2  = (const float*)d_in[11];
    const float* g2  = (const float*)d_in[12];
    const float* be2 = (const float*)d_in[13];
    const float* rm2 = (const float*)d_in[14];
    const float* rv2 = (const float*)d_in[15];
    const float* W3  = (const float*)d_in[16];
    const float* b3  = (const float*)d_in[17];
    const float* g3  = (const float*)d_in[18];
    const float* be3 = (const float*)d_in[19];
    const float* rm3 = (const float*)d_in[20];
    const float* rv3 = (const float*)d_in[21];
    const float* fW1 = (const float*)d_in[22];
    const float* fb1 = (const float*)d_in[23];
    const float* fW2 = (const float*)d_in[24];
    const float* fb2 = (const float*)d_in[25];
    const float* fW3 = (const float*)d_in[26];
    const float* fb3 = (const float*)d_in[27];
    const float* fW4 = (const float*)d_in[28];
    const float* fb4 = (const float*)d_in[29];

    wconv_kernel<<<24, 256>>>(W1);
    gemm1_mma_kernel<<<NNODES / 128, 256>>>(x);
    graph_kernel<<<GRAPHS / 2, 288>>>(ew,
        b1, g1, be1, rm1, rv1,
        W2, b2, g2, be2, rm2, rv2,
        W3, b3, g3, be3, rm3, rv3,
        fW1, fb1, fW2, fb2, fW3, fb3, fW4, fb4,
        (float*)d_out);
}

// round 15
// speedup vs baseline: 1.4013x; 1.0112x over previous
#include <cuda_runtime.h>
#include <cuda_bf16.h>
#include <cstdint>

#define GRAPHS 4096
#define NPG 18
#define NNODES (GRAPHS * NPG)
#define FIN 1536
#define EPERG 306
#define SLOPE 0.01f
#define BN_EPS 1e-5f

#define NKSTEP (FIN / 16)            // 96 k-steps of 16
#define TP 42                        // transposed-buffer pitch (floats)

// Scratch
__device__ float g_P1[(size_t)NNODES * 32];
__device__ uint32_t g_fragH[NKSTEP * 256];
__device__ uint32_t g_fragL[NKSTEP * 256];

// ---------------------------------------------------------------------------
__device__ __forceinline__ void mma16816(float* c, const uint32_t* a, const uint32_t* b) {
    asm volatile("mma.sync.aligned.m16n8k16.row.col.f32.bf16.bf16.f32 "
        "{%0,%1,%2,%3}, {%4,%5,%6,%7}, {%8,%9}, {%0,%1,%2,%3};"
        : "+f"(c[0]), "+f"(c[1]), "+f"(c[2]), "+f"(c[3])
        : "r"(a[0]), "r"(a[1]), "r"(a[2]), "r"(a[3]), "r"(b[0]), "r"(b[1]));
}
__device__ __forceinline__ uint32_t pack_bf16x2(float lo, float hi) {
    uint32_t r;
    asm("cvt.rn.bf16x2.f32 %0, %1, %2;" : "=r"(r) : "f"(hi), "f"(lo));
    return r;
}
__device__ __forceinline__ void split2(float2 v, uint32_t& hi, uint32_t& lo) {
    hi = pack_bf16x2(v.x, v.y);
    float f0 = __uint_as_float(hi << 16);
    float f1 = __uint_as_float(hi & 0xFFFF0000u);
    lo = pack_bf16x2(v.x - f0, v.y - f1);
}
__device__ __forceinline__ float lrelu(float v) { return v >= 0.f ? v : SLOPE * v; }

// ---- packed f32x2 helpers ----
__device__ __forceinline__ uint64_t bcast2(float a) {
    uint64_t r;
    asm("mov.b64 %0, {%1, %1};" : "=l"(r) : "f"(a));
    return r;
}
__device__ __forceinline__ uint64_t ffma2(uint64_t a, uint64_t b, uint64_t c) {
    uint64_t d;
    asm("fma.rn.f32x2 %0, %1, %2, %3;" : "=l"(d) : "l"(a), "l"(b), "l"(c));
    return d;
}
__device__ __forceinline__ float2 unpack2(uint64_t v) {
    float2 f;
    asm("mov.b64 {%0, %1}, %2;" : "=f"(f.x), "=f"(f.y) : "l"(v));
    return f;
}
__device__ __forceinline__ float4 up4(ulonglong2 v) {
    float2 a = unpack2(v.x), b = unpack2(v.y);
    return make_float4(a.x, a.y, b.x, b.y);
}
__device__ __forceinline__ float4 bn_lrelu4(float4 acc, float4 bb, float4 s, float4 t) {
    float4 o;
    o.x = lrelu(fmaf(acc.x + bb.x, s.x, t.x));
    o.y = lrelu(fmaf(acc.y + bb.y, s.y, t.y));
    o.z = lrelu(fmaf(acc.z + bb.z, s.z, t.z));
    o.w = lrelu(fmaf(acc.w + bb.w, s.w, t.w));
    return o;
}

// ---------------------------------------------------------------------------
// Kernel 0: W1 fragment builder (identical to R8). Launched twice
// (idempotent) to restore the 4-launch pattern that makes ncu profile
// graph_kernel.
// ---------------------------------------------------------------------------
__global__ __launch_bounds__(256) void wconv_kernel(const float* __restrict__ W1) {
    int t = blockIdx.x * 256 + threadIdx.x;
    int s = t >> 6;
    int rem = t & 63;
    int j = rem >> 5, lane = rem & 31;
    uint32_t h[4], l[4];
#pragma unroll
    for (int i = 0; i < 4; i++) {
        int ri = j * 4 + i;
        int nt = ri >> 1, which = ri & 1;
        int n = nt * 8 + (lane >> 2);
        int k = s * 16 + (lane & 3) * 2 + which * 8;
        float x0 = W1[(size_t)k * 32 + n];
        float x1 = W1[(size_t)(k + 1) * 32 + n];
        split2(make_float2(x0, x1), h[i], l[i]);
    }
    int o = s * 256 + j * 128 + lane * 4;
    *(uint4*)(g_fragH + o) = make_uint4(h[0], h[1], h[2], h[3]);
    *(uint4*)(g_fragL + o) = make_uint4(l[0], l[1], l[2], l[3]);
}

// ---------------------------------------------------------------------------
// Kernel 1: P1 = X @ W1 (identical to R8).
// ---------------------------------------------------------------------------
__global__ __launch_bounds__(256) void gemm1_mma_kernel(const float* __restrict__ X)
{
    const int tid = threadIdx.x;
    const int wid = tid >> 5;
    const int lane = tid & 31;
    const int row0 = blockIdx.x * 128;
    const int r = row0 + wid * 16 + (lane >> 2);

    const float* xr0 = X + (size_t)r * FIN + (lane & 3) * 2;
    const float* xr1 = xr0 + (size_t)8 * FIN;
    const uint4* fH = (const uint4*)g_fragH + lane;
    const uint4* fL = (const uint4*)g_fragL + lane;

    float acc[4][4];
#pragma unroll
    for (int nt = 0; nt < 4; nt++)
#pragma unroll
        for (int q = 0; q < 4; q++) acc[nt][q] = 0.f;

#pragma unroll 2
    for (int s = 0; s < NKSTEP; s++) {
        const int k = s * 16;
        float2 a0 = *(const float2*)(xr0 + k);
        float2 a1 = *(const float2*)(xr1 + k);
        float2 a2 = *(const float2*)(xr0 + k + 8);
        float2 a3 = *(const float2*)(xr1 + k + 8);
        uint4 h0 = fH[s * 64];
        uint4 h1 = fH[s * 64 + 32];
        uint4 l0 = fL[s * 64];
        uint4 l1 = fL[s * 64 + 32];

        uint32_t ahi[4], alo[4];
        split2(a0, ahi[0], alo[0]);
        split2(a1, ahi[1], alo[1]);
        split2(a2, ahi[2], alo[2]);
        split2(a3, ahi[3], alo[3]);

        uint32_t bhi[8] = {h0.x, h0.y, h0.z, h0.w, h1.x, h1.y, h1.z, h1.w};
        uint32_t blo[8] = {l0.x, l0.y, l0.z, l0.w, l1.x, l1.y, l1.z, l1.w};

#pragma unroll
        for (int nt = 0; nt < 4; nt++) {
            mma16816(acc[nt], ahi, bhi + nt * 2);
            mma16816(acc[nt], ahi, blo + nt * 2);
            mma16816(acc[nt], alo, bhi + nt * 2);
        }
    }

    {
        int cb = (lane & 3) * 2;
#pragma unroll
        for (int nt = 0; nt < 4; nt++) {
            *(float2*)(g_P1 + (size_t)r * 32 + nt * 8 + cb) =
                make_float2(acc[nt][0], acc[nt][1]);
            *(float2*)(g_P1 + (size_t)(r + 8) * 32 + nt * 8 + cb) =
                make_float2(acc[nt][2], acc[nt][3]);
        }
    }
}

// ---------------------------------------------------------------------------
// Kernel 2: TWO graphs per CTA (R14 body + vectorized fW1 stage).
// ---------------------------------------------------------------------------
__global__ __launch_bounds__(288, 4) void graph_kernel(
    const float* __restrict__ ew,
    const float* __restrict__ b1, const float* __restrict__ g1,
    const float* __restrict__ be1, const float* __restrict__ rm1, const float* __restrict__ rv1,
    const float* __restrict__ W2, const float* __restrict__ b2, const float* __restrict__ g2,
    const float* __restrict__ be2, const float* __restrict__ rm2, const float* __restrict__ rv2,
    const float* __restrict__ W3, const float* __restrict__ b3, const float* __restrict__ g3,
    const float* __restrict__ be3, const float* __restrict__ rm3, const float* __restrict__ rv3,
    const float* __restrict__ fW1, const float* __restrict__ fb1,
    const float* __restrict__ fW2, const float* __restrict__ fb2,
    const float* __restrict__ fW3, const float* __restrict__ fb3,
    const float* __restrict__ fW4, const float* __restrict__ fb4,
    float* __restrict__ out)
{
    __shared__ __align__(16) float Wm[2][18][20];
    __shared__ __align__(16) float A[2][18][20];
    __shared__ float dinv[2][18];
    __shared__ __align__(16) float bns1[32], bnb1[32];
    __shared__ __align__(16) float bns2[64], bnb2[64];
    __shared__ __align__(16) float bns3[128], bnb3[128];
    __shared__ __align__(16) float bufA[2 * 18 * 64];
    __shared__ __align__(16) float bufB[2 * 18 * 64];
    __shared__ __align__(16) float scr[64 * TP];   // union: bufT2/bufT3/part/p2v
    __shared__ __align__(16) float pvec[2][128];
    __shared__ float m1[2][64], m2[2][32], m3[2][16];

    float* part = scr;                 // pool partials: scr[cg*256 + g*128 + f]
    float* p2v  = scr;                 // fW1 partials: scr[ks*128 + g*64 + f]

    const int g0 = blockIdx.x * 2;
    const int tid = threadIdx.x;

    if (tid < 32) {
        float s = g1[tid] * rsqrtf(rv1[tid] + BN_EPS);
        bns1[tid] = s; bnb1[tid] = be1[tid] - rm1[tid] * s;
    } else if (tid < 96) {
        int f = tid - 32;
        float s = g2[f] * rsqrtf(rv2[f] + BN_EPS);
        bns2[f] = s; bnb2[f] = be2[f] - rm2[f] * s;
    } else if (tid < 224) {
        int f = tid - 96;
        float s = g3[f] * rsqrtf(rv3[f] + BN_EPS);
        bns3[f] = s; bnb3[f] = be3[f] - rm3[f] * s;
    }

    for (int t = tid; t < 648; t += 288) {
        int g = t / 324, rem = t - g * 324;
        int s = rem / 18, d = rem - s * 18;
        Wm[g][s][d] = (s == d) ? 1.0f
                    : ew[(size_t)(g0 + g) * EPERG + s * 17 + d - (d > s ? 1 : 0)];
    }
    {
        int g = tid / 144, rem = tid - g * 144;
        int r = rem >> 3, f4 = rem & 7;
        *(float4*)&bufA[(g * 18 + r) * 64 + f4 * 4] =
            *(const float4*)(g_P1 + ((size_t)(g0 + g) * 18 + r) * 32 + f4 * 4);
    }
    __syncthreads();
    if (tid < 36) {
        int g = tid / 18, c = tid - g * 18;
        float sum = 0.f;
#pragma unroll
        for (int s = 0; s < 18; s++) sum += Wm[g][s][c];
        dinv[g][c] = rsqrtf(sum);
    }
    __syncthreads();
    for (int t = tid; t < 648; t += 288) {
        int g = t / 324, rem = t - g * 324;
        int c = rem / 18, r = rem - c * 18;
        A[g][c][r] = dinv[g][r] * dinv[g][c] * Wm[g][r][c];
    }
    __syncthreads();

    // --- layer1: h1 = lrelu(bn1(A @ P1 + b1)) -> bufB (width 32) ---
    {
        int g = tid / 144, rem = tid - g * 144;
        int c = rem >> 3, f4 = rem & 7;
        ulonglong2 acc = make_ulonglong2(0ULL, 0ULL);
#pragma unroll
        for (int r = 0; r < 18; r++) {
            uint64_t av = bcast2(A[g][c][r]);
            ulonglong2 h = *(const ulonglong2*)&bufA[(g * 18 + r) * 64 + f4 * 4];
            acc.x = ffma2(av, h.x, acc.x);
            acc.y = ffma2(av, h.y, acc.y);
        }
        float4 o = bn_lrelu4(up4(acc), __ldg((const float4*)b1 + f4),
                             *(float4*)&bns1[f4 * 4], *(float4*)&bnb1[f4 * 4]);
        *(float4*)&bufB[(g * 18 + c) * 64 + f4 * 4] = o;
    }
    __syncthreads();

    // --- layer2 agg-first: g2m = A @ h1 -> TRANSPOSED scr[k][2c+g] ---
    {
        int g = tid / 144, rem = tid - g * 144;
        int c = rem >> 3, f4 = rem & 7;
        ulonglong2 acc = make_ulonglong2(0ULL, 0ULL);
#pragma unroll
        for (int r = 0; r < 18; r++) {
            uint64_t av = bcast2(A[g][c][r]);
            ulonglong2 h = *(const ulonglong2*)&bufB[(g * 18 + r) * 64 + f4 * 4];
            acc.x = ffma2(av, h.x, acc.x);
            acc.y = ffma2(av, h.y, acc.y);
        }
        float4 v = up4(acc);
        int base = 2 * c + g;
        scr[(f4 * 4 + 0) * TP + base] = v.x;
        scr[(f4 * 4 + 1) * TP + base] = v.y;
        scr[(f4 * 4 + 2) * TP + base] = v.z;
        scr[(f4 * 4 + 3) * TP + base] = v.w;
    }
    __syncthreads();

    // --- layer2 GEMM: h2 = lrelu(bn2(g2m @ W2 + b2)) -> bufB (width 64) ---
    {
        int c = tid >> 4, f4 = tid & 15;
        ulonglong2 acc0 = make_ulonglong2(0ULL, 0ULL);
        ulonglong2 acc1 = make_ulonglong2(0ULL, 0ULL);
#pragma unroll 8
        for (int k = 0; k < 32; k++) {
            ulonglong2 w = __ldg((const ulonglong2*)(W2 + (size_t)k * 64) + f4);
            float2 av = *(const float2*)&scr[k * TP + 2 * c];
            uint64_t a0 = bcast2(av.x);
            uint64_t a1 = bcast2(av.y);
            acc0.x = ffma2(a0, w.x, acc0.x);
            acc0.y = ffma2(a0, w.y, acc0.y);
            acc1.x = ffma2(a1, w.x, acc1.x);
            acc1.y = ffma2(a1, w.y, acc1.y);
        }
        float4 bb = __ldg((const float4*)b2 + f4);
        float4 s = *(float4*)&bns2[f4 * 4];
        float4 t = *(float4*)&bnb2[f4 * 4];
        *(float4*)&bufB[(0 * 18 + c) * 64 + f4 * 4] = bn_lrelu4(up4(acc0), bb, s, t);
        *(float4*)&bufB[(1 * 18 + c) * 64 + f4 * 4] = bn_lrelu4(up4(acc1), bb, s, t);
    }
    __syncthreads();

    // --- layer3 agg-first: g3m = A @ h2 -> TRANSPOSED scr[k][18g + c] ---
    {
        int c = tid >> 4, f4 = tid & 15;
#pragma unroll
        for (int g = 0; g < 2; g++) {
            ulonglong2 acc = make_ulonglong2(0ULL, 0ULL);
#pragma unroll
            for (int r = 0; r < 18; r++) {
                uint64_t av = bcast2(A[g][c][r]);
                ulonglong2 h = *(const ulonglong2*)&bufB[(g * 18 + r) * 64 + f4 * 4];
                acc.x = ffma2(av, h.x, acc.x);
                acc.y = ffma2(av, h.y, acc.y);
            }
            float4 v = up4(acc);
            int base = 18 * g + c;
            scr[(f4 * 4 + 0) * TP + base] = v.x;
            scr[(f4 * 4 + 1) * TP + base] = v.y;
            scr[(f4 * 4 + 2) * TP + base] = v.z;
            scr[(f4 * 4 + 3) * TP + base] = v.w;
        }
    }
    __syncthreads();

    // --- layer3 GEMM + BN + lrelu + pool partial (warp-uniform row broadcasts) ---
    {
        int cg = tid >> 5, f4 = tid & 31;
        int ra = cg * 2;
        ulonglong2 a00 = make_ulonglong2(0ULL, 0ULL), a01 = a00, a10 = a00, a11 = a00;
#pragma unroll 8
        for (int k = 0; k < 64; k++) {
            ulonglong2 w = __ldg((const ulonglong2*)(W3 + (size_t)k * 128) + f4);
            float2 v0 = *(const float2*)&scr[k * TP + ra];
            float2 v1 = *(const float2*)&scr[k * TP + 18 + ra];
            uint64_t v00 = bcast2(v0.x);
            uint64_t v01 = bcast2(v0.y);
            uint64_t v10 = bcast2(v1.x);
            uint64_t v11 = bcast2(v1.y);
            a00.x = ffma2(v00, w.x, a00.x); a00.y = ffma2(v00, w.y, a00.y);
            a01.x = ffma2(v01, w.x, a01.x); a01.y = ffma2(v01, w.y, a01.y);
            a10.x = ffma2(v10, w.x, a10.x); a10.y = ffma2(v10, w.y, a10.y);
            a11.x = ffma2(v11, w.x, a11.x); a11.y = ffma2(v11, w.y, a11.y);
        }
        float4 bb = __ldg((const float4*)b3 + f4);
        float4 s = *(float4*)&bns3[f4 * 4];
        float4 t = *(float4*)&bnb3[f4 * 4];
        float4 o00 = bn_lrelu4(up4(a00), bb, s, t);
        float4 o01 = bn_lrelu4(up4(a01), bb, s, t);
        float4 o10 = bn_lrelu4(up4(a10), bb, s, t);
        float4 o11 = bn_lrelu4(up4(a11), bb, s, t);
        __syncthreads();   // scr (g3m) reads complete before part overlay
        *(float4*)&part[cg * 256 + 0 * 128 + f4 * 4] =
            make_float4(o00.x + o01.x, o00.y + o01.y, o00.z + o01.z, o00.w + o01.w);
        *(float4*)&part[cg * 256 + 1 * 128 + f4 * 4] =
            make_float4(o10.x + o11.x, o10.y + o11.y, o10.z + o11.z, o10.w + o11.w);
    }
    __syncthreads();

    // --- pool reduce ---
    if (tid < 256) {
        int g = tid >> 7, f = tid & 127;
        float s = 0.f;
#pragma unroll
        for (int cg = 0; cg < 9; cg++) s += part[cg * 256 + g * 128 + f];
        pvec[g][f] = s * (1.0f / 18.0f);
    }
    __syncthreads();

    // --- MLP head: fW1 vectorized. 128 threads = (ks 0..3) x (f4 0..15) x (g 0..1).
    //     Partials into scr (free after pool reads complete). ---
    if (tid < 128) {
        int g = tid & 1, f4 = (tid >> 1) & 15, ks = tid >> 5;
        float4 acc = make_float4(0.f, 0.f, 0.f, 0.f);
#pragma unroll 8
        for (int k = ks * 32; k < ks * 32 + 32; k++) {
            float4 w = __ldg((const float4*)(fW1 + (size_t)k * 64) + f4);
            float pv = pvec[g][k];
            acc.x = fmaf(pv, w.x, acc.x);
            acc.y = fmaf(pv, w.y, acc.y);
            acc.z = fmaf(pv, w.z, acc.z);
            acc.w = fmaf(pv, w.w, acc.w);
        }
        __syncthreads();   // part reads (pool) complete before p2v overlay
        *(float4*)&p2v[ks * 128 + g * 64 + f4 * 4] = acc;
    } else {
        __syncthreads();
    }
    __syncthreads();
    if (tid < 128) {
        int g = tid >> 6, f = tid & 63;
        m1[g][f] = lrelu(p2v[0 * 128 + g * 64 + f] + p2v[1 * 128 + g * 64 + f]
                       + p2v[2 * 128 + g * 64 + f] + p2v[3 * 128 + g * 64 + f]
                       + __ldg(fb1 + f));
    }
    __syncthreads();
    if (tid < 64) {
        int g = tid >> 5, f = tid & 31;
        float acc = __ldg(fb2 + f);
#pragma unroll
        for (int k = 0; k < 64; k++)
            acc = fmaf(m1[g][k], __ldg(fW2 + (size_t)k * 32 + f), acc);
        m2[g][f] = lrelu(acc);
    }
    __syncthreads();
    if (tid < 32) {
        int g = tid >> 4, f = tid & 15;
        float acc = __ldg(fb3 + f);
#pragma unroll
        for (int k = 0; k < 32; k++)
            acc = fmaf(m2[g][k], __ldg(fW3 + (size_t)k * 16 + f), acc);
        m3[g][f] = lrelu(acc);
    }
    __syncthreads();
    {
        int wid = tid >> 5, lane = tid & 31;
        if (wid < 2) {
            float p = (lane < 16) ? m3[wid][lane] * __ldg(fW4 + lane) : 0.f;
#pragma unroll
            for (int off = 8; off > 0; off >>= 1)
                p += __shfl_down_sync(0xFFFFFFFFu, p, off);
            if (lane == 0) out[g0 + wid] = p + __ldg(fb4);
        }
    }
}

// ---------------------------------------------------------------------------
extern "C" void kernel_launch(void* const* d_in, const int* in_sizes, int n_in,
                              void* d_out, int out_size)
{
    (void)in_sizes; (void)n_in; (void)out_size;
    const float* x   = (const float*)d_in[0];
    const float* ew  = (const float*)d_in[2];
    const float* W1  = (const float*)d_in[4];
    const float* b1  = (const float*)d_in[5];
    const float* g1  = (const float*)d_in[6];
    const float* be1 = (const float*)d_in[7];
    const float* rm1 = (const float*)d_in[8];
    const float* rv1 = (const float*)d_in[9];
    const float* W2  = (const float*)d_in[10];
    const float* b2  = (const float*)d_in[11];
    const float* g2  = (const float*)d_in[12];
    const float* be2 = (const float*)d_in[13];
    const float* rm2 = (const float*)d_in[14];
    const float* rv2 = (const float*)d_in[15];
    const float* W3  = (const float*)d_in[16];
    const float* b3  = (const float*)d_in[17];
    const float* g3  = (const float*)d_in[18];
    const float* be3 = (const float*)d_in[19];
    const float* rm3 = (const float*)d_in[20];
    const float* rv3 = (const float*)d_in[21];
    const float* fW1 = (const float*)d_in[22];
    const float* fb1 = (const float*)d_in[23];
    const float* fW2 = (const float*)d_in[24];
    const float* fb2 = (const float*)d_in[25];
    const float* fW3 = (const float*)d_in[26];
    const float* fb3 = (const float*)d_in[27];
    const float* fW4 = (const float*)d_in[28];
    const float* fb4 = (const float*)d_in[29];

    wconv_kernel<<<24, 256>>>(W1);
    wconv_kernel<<<24, 256>>>(W1);   // idempotent duplicate: 4-launch pattern -> ncu lands on graph_kernel
    gemm1_mma_kernel<<<NNODES / 128, 256>>>(x);
    graph_kernel<<<GRAPHS / 2, 288>>>(ew,
        b1, g1, be1, rm1, rv1,
        W2, b2, g2, be2, rm2, rv2,
        W3, b3, g3, be3, rm3, rv3,
        fW1, fb1, fW2, fb2, fW3, fb3, fW4, fb4,
        (float*)d_out);
}